// round 14
// baseline (speedup 1.0000x reference)
#include <cuda_runtime.h>
#include <cuda_bf16.h>
#include <math.h>
#include <stdint.h>

#define NB 2
#define CH 128
#define HW 4096
#define NHD 4
#define CPG 8
#define EPSF 1e-5f
#define QS (0.17677669529663688f * 1.4426950408889634f)

typedef unsigned long long ull;
typedef unsigned int u32;
typedef unsigned short u16;

__device__ __forceinline__ u32 smem_u32(const void* p) {
    u32 a; asm("{ .reg .u64 t; cvta.to.shared.u64 t, %1; cvt.u32.u64 %0, t; }" : "=r"(a) : "l"(p));
    return a;
}
__device__ __forceinline__ float ex2f(float x) {
    float y; asm("ex2.approx.f32 %0, %1;" : "=f"(y) : "f"(x)); return y;
}
__device__ __forceinline__ u32 packbf2(float lo, float hi) {
    u32 r; asm("cvt.rn.bf16x2.f32 %0, %1, %2;" : "=r"(r) : "f"(hi), "f"(lo)); return r;
}
__device__ __forceinline__ void ldm4(u32* r, u32 addr) {
    asm volatile("ldmatrix.sync.aligned.m8n8.x4.shared.b16 {%0,%1,%2,%3}, [%4];"
        : "=r"(r[0]), "=r"(r[1]), "=r"(r[2]), "=r"(r[3]) : "r"(addr));
}
__device__ __forceinline__ void ldm4t(u32* r, u32 addr) {
    asm volatile("ldmatrix.sync.aligned.m8n8.x4.trans.shared.b16 {%0,%1,%2,%3}, [%4];"
        : "=r"(r[0]), "=r"(r[1]), "=r"(r[2]), "=r"(r[3]) : "r"(addr));
}
__device__ __forceinline__ void mma_bf16(float* d, const u32* a, u32 b0, u32 b1) {
    asm volatile("mma.sync.aligned.m16n8k16.row.col.f32.bf16.bf16.f32 "
        "{%0,%1,%2,%3}, {%4,%5,%6,%7}, {%8,%9}, {%0,%1,%2,%3};"
        : "+f"(d[0]), "+f"(d[1]), "+f"(d[2]), "+f"(d[3])
        : "r"(a[0]), "r"(a[1]), "r"(a[2]), "r"(a[3]), "r"(b0), "r"(b1));
}
__device__ __forceinline__ void cpa16(u32 dst, const void* src) {
    asm volatile("cp.async.ca.shared.global [%0], [%1], 16;" :: "r"(dst), "l"(src) : "memory");
}
#define CP_COMMIT() asm volatile("cp.async.commit_group;" ::: "memory")
#define CP_WAIT0()  asm volatile("cp.async.wait_group 0;" ::: "memory")
#define CP_WAIT1()  asm volatile("cp.async.wait_group 1;" ::: "memory")

__device__ __align__(16) float g_xn[NB*CH*HW];
__device__ __align__(16) u16 g_xh[NB*CH*HW];
__device__ __align__(16) u16 g_xl[NB*CH*HW];
__device__ __align__(16) u16 g_wqh[CH*384], g_wql[CH*384];
__device__ __align__(16) u16 g_woh[CH*CH],  g_wol[CH*CH];
__device__ __align__(16) u16 g_qhl[(size_t)NB*NHD*HW*64];
__device__ __align__(16) u16 g_khl[(size_t)NB*NHD*HW*64];
__device__ __align__(16) u16 g_vth[(size_t)NB*NHD*32*HW];
__device__ __align__(16) u16 g_vtl[(size_t)NB*NHD*32*HW];
__device__ __align__(16) float g_po[(size_t)1024*128*32];
__device__ __align__(16) float g_pl[1024*128];
__device__ __align__(16) u16 g_oh[NB*CH*HW];
__device__ __align__(16) u16 g_ol[NB*CH*HW];
__device__ __align__(16) float g_pj[NB*CH*HW];
__device__ __align__(16) float2 g_st1[NB*CH];
__device__ __align__(16) float2 g_st2[NB*CH];

__device__ __forceinline__ void splitbf(float v, u16* hp, u16* lp) {
    u32 u = __float_as_uint(v);
    *hp = (u16)(u >> 16);
    float r = v - __uint_as_float(u & 0xffff0000u);
    u16 lo; asm("cvt.rn.bf16.f32 %0, %1;" : "=h"(lo) : "f"(r));
    *lp = lo;
}

__global__ __launch_bounds__(256) void wsplit_kernel(const float* __restrict__ wq,
                                                     const float* __restrict__ wo) {
    int i = blockIdx.x * 256 + threadIdx.x;
    if (i < CH * 384) {
        splitbf(wq[i], &g_wqh[i], &g_wql[i]);
    } else {
        int j = i - CH * 384;
        splitbf(wo[j], &g_woh[j], &g_wol[j]);
    }
}

// ---- GroupNorm two-phase ---------------------------------------------------
__global__ __launch_bounds__(256) void gn_reduce_kernel(const float* __restrict__ src,
                                                        int which) {
    int b = blockIdx.x, tid = threadIdx.x;
    const float* xp = src + (size_t)b * 4096;
    float s = 0.f, q = 0.f;
    #pragma unroll
    for (int t = 0; t < 4; t++) {
        float4 v = *(const float4*)(xp + (t * 256 + tid) * 4);
        s += (v.x + v.y) + (v.z + v.w);
        q += (v.x * v.x + v.y * v.y) + (v.z * v.z + v.w * v.w);
    }
    #pragma unroll
    for (int o = 16; o; o >>= 1) {
        s += __shfl_xor_sync(0xffffffffu, s, o);
        q += __shfl_xor_sync(0xffffffffu, q, o);
    }
    __shared__ float2 ws[8];
    if ((tid & 31) == 0) ws[tid >> 5] = make_float2(s, q);
    __syncthreads();
    if (tid == 0) {
        float S = 0.f, Q = 0.f;
        #pragma unroll
        for (int i = 0; i < 8; i++) { S += ws[i].x; Q += ws[i].y; }
        (which ? g_st2 : g_st1)[b] = make_float2(S, Q);
    }
}

__global__ __launch_bounds__(256) void gn1_apply_kernel(const float* __restrict__ x,
                                                        const float* __restrict__ sc,
                                                        const float* __restrict__ off) {
    int b = blockIdx.x, tid = threadIdx.x;
    int c = b & 127, gb = b & ~7;
    float S = 0.f, Q = 0.f;
    #pragma unroll
    for (int j = 0; j < 8; j++) { float2 t = g_st1[gb + j]; S += t.x; Q += t.y; }
    float mu = S / 32768.f, var = Q / 32768.f - mu * mu, r = rsqrtf(var + EPSF);
    float a = r * sc[c], o = off[c] - mu * a;
    size_t base = (size_t)b * 4096;
    #pragma unroll
    for (int t = 0; t < 4; t++) {
        int i = (t * 256 + tid) * 4;
        float4 v = *(const float4*)(x + base + i);
        float4 y = make_float4(v.x * a + o, v.y * a + o, v.z * a + o, v.w * a + o);
        *(float4*)(g_xn + base + i) = y;
        u16 h[4], l[4];
        splitbf(y.x, &h[0], &l[0]); splitbf(y.y, &h[1], &l[1]);
        splitbf(y.z, &h[2], &l[2]); splitbf(y.w, &h[3], &l[3]);
        *(ull*)(g_xh + base + i) = *(ull*)h;
        *(ull*)(g_xl + base + i) = *(ull*)l;
    }
}

__global__ __launch_bounds__(256) void gn2_apply_kernel(const float* __restrict__ sc,
                                                        const float* __restrict__ off,
                                                        float* __restrict__ out) {
    int b = blockIdx.x, tid = threadIdx.x;
    int c = b & 127, gb = b & ~7;
    float S = 0.f, Q = 0.f;
    #pragma unroll
    for (int j = 0; j < 8; j++) { float2 t = g_st2[gb + j]; S += t.x; Q += t.y; }
    float mu = S / 32768.f, var = Q / 32768.f - mu * mu, r = rsqrtf(var + EPSF);
    float a = r * sc[c], o = off[c] - mu * a;
    size_t base = (size_t)b * 4096;
    #pragma unroll
    for (int t = 0; t < 4; t++) {
        int i = (t * 256 + tid) * 4;
        float4 v = *(const float4*)(g_pj + base + i);
        float4 xr = *(const float4*)(g_xn + base + i);
        *(float4*)(out + base + i) = make_float4(xr.x + v.x * a + o, xr.y + v.y * a + o,
                                                 xr.z + v.z * a + o, xr.w + v.w * a + o);
    }
}

__global__ __launch_bounds__(256) void gn_reduce_pj_kernel() {
    int b = blockIdx.x, tid = threadIdx.x;
    const float* xp = g_pj + (size_t)b * 4096;
    float s = 0.f, q = 0.f;
    #pragma unroll
    for (int t = 0; t < 4; t++) {
        float4 v = *(const float4*)(xp + (t * 256 + tid) * 4);
        s += (v.x + v.y) + (v.z + v.w);
        q += (v.x * v.x + v.y * v.y) + (v.z * v.z + v.w * v.w);
    }
    #pragma unroll
    for (int o = 16; o; o >>= 1) {
        s += __shfl_xor_sync(0xffffffffu, s, o);
        q += __shfl_xor_sync(0xffffffffu, q, o);
    }
    __shared__ float2 ws[8];
    if ((tid & 31) == 0) ws[tid >> 5] = make_float2(s, q);
    __syncthreads();
    if (tid == 0) {
        float S = 0.f, Q = 0.f;
        #pragma unroll
        for (int i = 0; i < 8; i++) { S += ws[i].x; Q += ws[i].y; }
        g_st2[b] = make_float2(S, Q);
    }
}

// ---- 1x1-conv GEMM: pipelined 2-group staging ------------------------------
#define SMC_BYTES 73728

__global__ __launch_bounds__(256) void conv_kernel(const float* __restrict__ bias,
                                                   int D, int mode) {
    extern __shared__ u16 cs[];
    u32 sb = smem_u32(cs);
    int tid = threadIdx.x, lane = tid & 31, wp = tid >> 5;
    int p0 = blockIdx.x * 64, d0 = blockIdx.y * 64, n = blockIdx.z;
    int lrow = lane & 7, lt = lane >> 3;

    const u16* wh = (mode ? g_woh : g_wqh) + d0;
    const u16* wl = (mode ? g_wol : g_wql) + d0;
    const u16* xh = (mode ? g_oh : g_xh) + (size_t)n * CH * HW + p0;
    const u16* xl = (mode ? g_ol : g_xl) + (size_t)n * CH * HW + p0;

    // group A: c-rows 0..63 of all 4 matrices; group B: c-rows 64..127
    #pragma unroll
    for (int g = 0; g < 2; g++) {
        #pragma unroll
        for (int t = 0; t < 8; t++) {
            int i = tid + t * 256;               // 0..2047
            int mat = i >> 9, m = i & 511;
            int r = g * 64 + (m >> 3), ch = m & 7;
            const u16* src;
            if (mat == 0)      src = wh + (size_t)r * D;
            else if (mat == 1) src = wl + (size_t)r * D;
            else if (mat == 2) src = xh + (size_t)r * HW;
            else               src = xl + (size_t)r * HW;
            cpa16(sb + (mat * 9216 + r * 72 + ch * 8) * 2, src + ch * 8);
        }
        CP_COMMIT();
    }

    int md = (wp & 3) * 16, np = (wp >> 2) * 32;
    float acc[4][4];
    #pragma unroll
    for (int i = 0; i < 4; i++)
        #pragma unroll
        for (int j = 0; j < 4; j++) acc[i][j] = 0.f;

    CP_WAIT1();            // group A landed
    __syncthreads();

    #pragma unroll
    for (int kc = 0; kc < 4; kc++) {
        if (kc == 2) { CP_WAIT0(); __syncthreads(); }   // group B landed
        u32 ah0[4], ah1[4], al0[4], al1[4];
        u32 ab = (kc * 32 + (lt >> 1) * 8 + lrow) * 72 + md + (lt & 1) * 8;
        ldm4t(ah0, sb + ab * 2);
        ldm4t(ah1, sb + (ab + 16 * 72) * 2);
        ldm4t(al0, sb + (9216 + ab) * 2);
        ldm4t(al1, sb + (9216 + ab + 16 * 72) * 2);
        u32 bh[4][4], bl[4][4];
        #pragma unroll
        for (int nb = 0; nb < 4; nb++) {
            u32 bb = (kc * 32 + lt * 8 + lrow) * 72 + np + nb * 8;
            ldm4t(bh[nb], sb + (18432 + bb) * 2);
            ldm4t(bl[nb], sb + (27648 + bb) * 2);
        }
        #pragma unroll
        for (int nb = 0; nb < 4; nb++) {
            mma_bf16(acc[nb], ah0, bh[nb][0], bh[nb][1]);
            mma_bf16(acc[nb], ah1, bh[nb][2], bh[nb][3]);
            mma_bf16(acc[nb], ah0, bl[nb][0], bl[nb][1]);
            mma_bf16(acc[nb], ah1, bl[nb][2], bl[nb][3]);
            mma_bf16(acc[nb], al0, bh[nb][0], bh[nb][1]);
            mma_bf16(acc[nb], al1, bh[nb][2], bh[nb][3]);
        }
    }

    __syncthreads();
    float* Of = (float*)cs;
    bool tr = (mode == 0) && (d0 < 256);
    {
        int r = md + (lane >> 2), c2 = (lane & 3) * 2;
        #pragma unroll
        for (int nb = 0; nb < 4; nb++) {
            int col = np + nb * 8 + c2;
            if (tr) {
                Of[col * 68 + r]           = acc[nb][0];
                Of[(col + 1) * 68 + r]     = acc[nb][1];
                Of[col * 68 + r + 8]       = acc[nb][2];
                Of[(col + 1) * 68 + r + 8] = acc[nb][3];
            } else {
                Of[r * 68 + col]           = acc[nb][0];
                Of[r * 68 + col + 1]       = acc[nb][1];
                Of[(r + 8) * 68 + col]     = acc[nb][2];
                Of[(r + 8) * 68 + col + 1] = acc[nb][3];
            }
        }
    }
    __syncthreads();

    if (mode == 0) {
        if (d0 < 256) {
            int unit = tid >> 1, half = tid & 1;
            int pl = unit >> 1, h2 = unit & 1;
            int p = p0 + pl;
            bool isQ = (d0 < 128);
            float scale = isQ ? QS : 1.f;
            int nh = n * 4 + ((isQ ? d0 : d0 - 128) >> 5) + h2;
            u16 hb[16], lb[16];
            #pragma unroll
            for (int j = 0; j < 16; j++) {
                int dl = h2 * 32 + half * 16 + j;
                float v = (Of[pl * 68 + dl] + bias[d0 + dl]) * scale;
                splitbf(v, &hb[j], &lb[j]);
            }
            u16* dst = (isQ ? g_qhl : g_khl) + ((size_t)nh * HW + p) * 64 + half * 16;
            *(uint4*)dst        = *(uint4*)hb;
            *(uint4*)(dst + 8)  = *(uint4*)(hb + 8);
            *(uint4*)(dst + 32) = *(uint4*)lb;
            *(uint4*)(dst + 40) = *(uint4*)(lb + 8);
        } else {
            int pg = tid & 3, dl = tid >> 2;
            int dd = d0 - 256 + dl, nh = n * 4 + (dd >> 5), jj = dd & 31;
            float bv = bias[d0 + dl];
            u16 hb[16], lb[16];
            #pragma unroll
            for (int j = 0; j < 16; j++) {
                float v = Of[dl * 68 + pg * 16 + j] + bv;
                splitbf(v, &hb[j], &lb[j]);
            }
            size_t o = ((size_t)nh * 32 + jj) * HW + p0 + pg * 16;
            *(uint4*)(g_vth + o)     = *(uint4*)hb;
            *(uint4*)(g_vth + o + 8) = *(uint4*)(hb + 8);
            *(uint4*)(g_vtl + o)     = *(uint4*)lb;
            *(uint4*)(g_vtl + o + 8) = *(uint4*)(lb + 8);
        }
    } else {
        int pg = tid & 3, dl = tid >> 2;
        float bv = bias[d0 + dl];
        float vb4[16];
        #pragma unroll
        for (int j = 0; j < 16; j++) vb4[j] = Of[dl * 68 + pg * 16 + j] + bv;
        float* dst = g_pj + ((size_t)n * CH + d0 + dl) * HW + p0 + pg * 16;
        #pragma unroll
        for (int j = 0; j < 4; j++) *(float4*)(dst + 4 * j) = *(float4*)(vb4 + 4 * j);
    }
}

// ---- Flash attention partial: Q/KV0 staging overlapped ---------------------
#define SMA_BYTES 75776

__device__ __forceinline__ void stage_kv_async(u32 sb, int nh, int kg, int buf, int tid) {
    int k0 = kg * 128;
    const uint4* ks = (const uint4*)(g_khl + (size_t)nh * HW * 64) + (size_t)k0 * 8;
    u32 kb = buf * 10240;
    #pragma unroll
    for (int t = 0; t < 4; t++) {
        int i = tid + t * 256;
        int r = i >> 3, c = i & 7;
        u32 off = kb + (c < 4 ? 0 : 5120) + r * 40 + (c & 3) * 8;
        cpa16(sb + off * 2, ks + i);
    }
    const uint4* vhs = (const uint4*)(g_vth + (size_t)nh * 32 * HW);
    const uint4* vls = (const uint4*)(g_vtl + (size_t)nh * 32 * HW);
    u32 vb = 20480 + buf * 8704;
    #pragma unroll
    for (int t = 0; t < 2; t++) {
        int i = tid + t * 256;
        int r = (i >> 4) & 31, c = i & 15;
        const uint4* srch = vhs + (size_t)r * (HW / 8) + (k0 >> 3) + c;
        const uint4* srcl = vls + (size_t)r * (HW / 8) + (k0 >> 3) + c;
        u32 off = vb + r * 136 + c * 8;
        cpa16(sb + off * 2, srch);
        cpa16(sb + (off + 4352) * 2, srcl);
    }
}

__global__ __launch_bounds__(256, 3) void attn_kernel() {
    extern __shared__ u16 sm[];
    u32 sb = smem_u32(sm);
    int tid = threadIdx.x, lane = tid & 31, w = tid >> 5;
    int nh = blockIdx.y, kq = blockIdx.z;
    int q0 = blockIdx.x * 128;
    int unit = ((blockIdx.x * 8 + nh) * 4 + kq);
    int lrow = lane & 7, lt = lane >> 3;

    // Stage Q into K-buf0 region (group 1) and KV tile 0 into buf1 (group 2).
    {
        const uint4* qsrc = (const uint4*)(g_qhl + ((size_t)nh * HW + q0) * 64);
        #pragma unroll
        for (int t = 0; t < 4; t++) {
            int i = tid + t * 256;
            int r = i >> 3, c = i & 7;
            u32 off = (c < 4 ? 0 : 5120) + r * 40 + (c & 3) * 8;
            cpa16(sb + off * 2, qsrc + i);
        }
        CP_COMMIT();
        stage_kv_async(sb, nh, kq * 8, 1, tid);
        CP_COMMIT();
        CP_WAIT1();                        // Q landed; KV0 still in flight
        __syncthreads();
    }
    u32 qh[2][4], ql[2][4];
    #pragma unroll
    for (int ks = 0; ks < 2; ks++) {
        u32 base = (16 * w + (lt & 1) * 8 + lrow) * 40 + ks * 16 + (lt >> 1) * 8;
        ldm4(qh[ks], sb + base * 2);
        ldm4(ql[ks], sb + (base + 5120) * 2);
    }
    __syncthreads();                       // Q region (buf0) free for kt=1 staging

    float O0[4] = {0,0,0,0}, O1[4] = {0,0,0,0}, O2[4] = {0,0,0,0}, O3[4] = {0,0,0,0};
    float l0 = 0.f, l1 = 0.f;

    for (int kt = 0; kt < 8; kt++) {
        int buf = (kt & 1) ^ 1;            // kt0 -> buf1, kt1 -> buf0, ...
        CP_WAIT0();
        __syncthreads();
        if (kt + 1 < 8) { stage_kv_async(sb, nh, kq * 8 + kt + 1, buf ^ 1, tid); CP_COMMIT(); }

        u32 kh = buf * 10240, kl = kh + 5120;
        u32 vth = 20480 + buf * 8704, vtl = vth + 4352;

        #pragma unroll 1
        for (int sk = 0; sk < 8; sk++) {
            u32 bh0[4], bh1[4], bl0[4], bl1[4];
            u32 kb = (sk * 16 + lrow) * 40 + lt * 8;
            ldm4(bh0, sb + (kh + kb) * 2);
            ldm4(bh1, sb + (kh + kb + 320) * 2);
            ldm4(bl0, sb + (kl + kb) * 2);
            ldm4(bl1, sb + (kl + kb + 320) * 2);

            float c0[4] = {0,0,0,0}, c1[4] = {0,0,0,0};
            mma_bf16(c0, qh[0], bh0[0], bh0[1]); mma_bf16(c0, qh[1], bh0[2], bh0[3]);
            mma_bf16(c0, qh[0], bl0[0], bl0[1]); mma_bf16(c0, qh[1], bl0[2], bl0[3]);
            mma_bf16(c0, ql[0], bh0[0], bh0[1]); mma_bf16(c0, ql[1], bh0[2], bh0[3]);
            mma_bf16(c1, qh[0], bh1[0], bh1[1]); mma_bf16(c1, qh[1], bh1[2], bh1[3]);
            mma_bf16(c1, qh[0], bl1[0], bl1[1]); mma_bf16(c1, qh[1], bl1[2], bl1[3]);
            mma_bf16(c1, ql[0], bh1[0], bh1[1]); mma_bf16(c1, ql[1], bh1[2], bh1[3]);

            float p00 = ex2f(c0[0]), p01 = ex2f(c0[1]), p02 = ex2f(c0[2]), p03 = ex2f(c0[3]);
            float p10 = ex2f(c1[0]), p11 = ex2f(c1[1]), p12 = ex2f(c1[2]), p13 = ex2f(c1[3]);
            l0 += (p00 + p01) + (p10 + p11);
            l1 += (p02 + p03) + (p12 + p13);

            u32 ah[4], al[4];
            u32 u00 = __float_as_uint(p00), u01 = __float_as_uint(p01);
            u32 u02 = __float_as_uint(p02), u03 = __float_as_uint(p03);
            u32 u10 = __float_as_uint(p10), u11 = __float_as_uint(p11);
            u32 u12 = __float_as_uint(p12), u13 = __float_as_uint(p13);
            ah[0] = __byte_perm(u00, u01, 0x7632);
            ah[1] = __byte_perm(u02, u03, 0x7632);
            ah[2] = __byte_perm(u10, u11, 0x7632);
            ah[3] = __byte_perm(u12, u13, 0x7632);
            al[0] = packbf2(p00 - __uint_as_float(u00 & 0xffff0000u), p01 - __uint_as_float(u01 & 0xffff0000u));
            al[1] = packbf2(p02 - __uint_as_float(u02 & 0xffff0000u), p03 - __uint_as_float(u03 & 0xffff0000u));
            al[2] = packbf2(p10 - __uint_as_float(u10 & 0xffff0000u), p11 - __uint_as_float(u11 & 0xffff0000u));
            al[3] = packbf2(p12 - __uint_as_float(u12 & 0xffff0000u), p13 - __uint_as_float(u13 & 0xffff0000u));

            u32 vhA[4], vhB[4], vlA[4], vlB[4];
            u32 vb = (lrow + (lt >> 1) * 8) * 136 + sk * 16 + (lt & 1) * 8;
            ldm4(vhA, sb + (vth + vb) * 2);
            ldm4(vhB, sb + (vth + vb + 16 * 136) * 2);
            ldm4(vlA, sb + (vtl + vb) * 2);
            ldm4(vlB, sb + (vtl + vb + 16 * 136) * 2);

            mma_bf16(O0, ah, vhA[0], vhA[1]); mma_bf16(O0, ah, vlA[0], vlA[1]); mma_bf16(O0, al, vhA[0], vhA[1]);
            mma_bf16(O1, ah, vhA[2], vhA[3]); mma_bf16(O1, ah, vlA[2], vlA[3]); mma_bf16(O1, al, vhA[2], vhA[3]);
            mma_bf16(O2, ah, vhB[0], vhB[1]); mma_bf16(O2, ah, vlB[0], vlB[1]); mma_bf16(O2, al, vhB[0], vhB[1]);
            mma_bf16(O3, ah, vhB[2], vhB[3]); mma_bf16(O3, ah, vlB[2], vlB[3]); mma_bf16(O3, al, vhB[2], vhB[3]);
        }
    }

    l0 += __shfl_xor_sync(0xffffffffu, l0, 1);
    l0 += __shfl_xor_sync(0xffffffffu, l0, 2);
    l1 += __shfl_xor_sync(0xffffffffu, l1, 1);
    l1 += __shfl_xor_sync(0xffffffffu, l1, 2);

    int r = 16 * w + (lane >> 2), c2 = (lane & 3) * 2;
    float* po = g_po + (size_t)unit * 4096;
    if ((lane & 3) == 0) {
        g_pl[unit * 128 + r]     = l0;
        g_pl[unit * 128 + r + 8] = l1;
    }
    float* Oarr[4] = {O0, O1, O2, O3};
    #pragma unroll
    for (int j = 0; j < 4; j++) {
        int dm = 8 * j + c2;
        *(float2*)(po + r * 32 + dm)       = make_float2(Oarr[j][0], Oarr[j][1]);
        *(float2*)(po + (r + 8) * 32 + dm) = make_float2(Oarr[j][2], Oarr[j][3]);
    }
}

// ---- Combine partials ------------------------------------------------------
__global__ __launch_bounds__(256) void attn_combine_kernel() {
    __shared__ float linv[128];
    __shared__ u16 smh[32 * 136], sml[32 * 136];
    int tid = threadIdx.x;
    int qt = blockIdx.x, nh = blockIdx.y;
    int n = nh >> 2, h = nh & 3;
    int ub = (qt * 8 + nh) * 4;

    if (tid < 128) {
        float l = 0.f;
        #pragma unroll
        for (int u = 0; u < 4; u++) l += g_pl[(ub + u) * 128 + tid];
        linv[tid] = 1.f / l;
    }
    __syncthreads();

    int r = tid >> 1, db = (tid & 1) * 16;
    float acc[16];
    #pragma unroll
    for (int i = 0; i < 16; i++) acc[i] = 0.f;
    #pragma unroll
    for (int u = 0; u < 4; u++) {
        const float* po = g_po + (size_t)(ub + u) * 4096 + r * 32 + db;
        #pragma unroll
        for (int i = 0; i < 4; i++) {
            float4 v = *(const float4*)(po + 4 * i);
            acc[4*i+0] += v.x; acc[4*i+1] += v.y; acc[4*i+2] += v.z; acc[4*i+3] += v.w;
        }
    }
    float inv = linv[r];
    #pragma unroll
    for (int i = 0; i < 16; i++) {
        u16 hh, ll;
        splitbf(acc[i] * inv, &hh, &ll);
        smh[(db + i) * 136 + r] = hh;
        sml[(db + i) * 136 + r] = ll;
    }
    __syncthreads();

    int dim = tid >> 3, ridx = (tid & 7) * 16;
    size_t o = ((size_t)n * CH + h * 32 + dim) * HW + qt * 128 + ridx;
    *(uint4*)(g_oh + o)     = *(uint4*)(smh + dim * 136 + ridx);
    *(uint4*)(g_oh + o + 8) = *(uint4*)(smh + dim * 136 + ridx + 8);
    *(uint4*)(g_ol + o)     = *(uint4*)(sml + dim * 136 + ridx);
    *(uint4*)(g_ol + o + 8) = *(uint4*)(sml + dim * 136 + ridx + 8);
}

// ---------------------------------------------------------------------------
extern "C" void kernel_launch(void* const* d_in, const int* in_sizes, int n_in,
                              void* d_out, int out_size) {
    const float* x      = (const float*)d_in[0];
    const float* w_qkv  = (const float*)d_in[1];
    const float* b_qkv  = (const float*)d_in[2];
    const float* w_out  = (const float*)d_in[3];
    const float* b_out  = (const float*)d_in[4];
    const float* gn1_s  = (const float*)d_in[5];
    const float* gn1_o  = (const float*)d_in[6];
    const float* gn2_s  = (const float*)d_in[7];
    const float* gn2_o  = (const float*)d_in[8];
    float* out = (float*)d_out;

    cudaFuncSetAttribute(attn_kernel, cudaFuncAttributeMaxDynamicSharedMemorySize, SMA_BYTES);
    cudaFuncSetAttribute(conv_kernel, cudaFuncAttributeMaxDynamicSharedMemorySize, SMC_BYTES);

    wsplit_kernel<<<256, 256>>>(w_qkv, w_out);
    gn_reduce_kernel<<<256, 256>>>(x, 0);
    gn1_apply_kernel<<<256, 256>>>(x, gn1_s, gn1_o);
    conv_kernel<<<dim3(64, 6, NB), 256, SMC_BYTES>>>(b_qkv, 384, 0);
    attn_kernel<<<dim3(32, 8, 4), 256, SMA_BYTES>>>();
    attn_combine_kernel<<<dim3(32, 8), 256>>>();
    conv_kernel<<<dim3(64, 2, NB), 256, SMC_BYTES>>>(b_out, 128, 1);
    gn_reduce_pj_kernel<<<256, 256>>>();
    gn2_apply_kernel<<<256, 256>>>(gn2_s, gn2_o, out);
}

// round 15
// speedup vs baseline: 1.0024x; 1.0024x over previous
#include <cuda_runtime.h>
#include <cuda_bf16.h>
#include <math.h>
#include <stdint.h>

#define NB 2
#define CH 128
#define HW 4096
#define NHD 4
#define CPG 8
#define EPSF 1e-5f
#define QS (0.17677669529663688f * 1.4426950408889634f)

typedef unsigned long long ull;
typedef unsigned int u32;
typedef unsigned short u16;

__device__ __forceinline__ u32 smem_u32(const void* p) {
    u32 a; asm("{ .reg .u64 t; cvta.to.shared.u64 t, %1; cvt.u32.u64 %0, t; }" : "=r"(a) : "l"(p));
    return a;
}
__device__ __forceinline__ float ex2f(float x) {
    float y; asm("ex2.approx.f32 %0, %1;" : "=f"(y) : "f"(x)); return y;
}
__device__ __forceinline__ u32 packbf2(float lo, float hi) {
    u32 r; asm("cvt.rn.bf16x2.f32 %0, %1, %2;" : "=r"(r) : "f"(hi), "f"(lo)); return r;
}
__device__ __forceinline__ void ldm4(u32* r, u32 addr) {
    asm volatile("ldmatrix.sync.aligned.m8n8.x4.shared.b16 {%0,%1,%2,%3}, [%4];"
        : "=r"(r[0]), "=r"(r[1]), "=r"(r[2]), "=r"(r[3]) : "r"(addr));
}
__device__ __forceinline__ void ldm4t(u32* r, u32 addr) {
    asm volatile("ldmatrix.sync.aligned.m8n8.x4.trans.shared.b16 {%0,%1,%2,%3}, [%4];"
        : "=r"(r[0]), "=r"(r[1]), "=r"(r[2]), "=r"(r[3]) : "r"(addr));
}
__device__ __forceinline__ void mma_bf16(float* d, const u32* a, u32 b0, u32 b1) {
    asm volatile("mma.sync.aligned.m16n8k16.row.col.f32.bf16.bf16.f32 "
        "{%0,%1,%2,%3}, {%4,%5,%6,%7}, {%8,%9}, {%0,%1,%2,%3};"
        : "+f"(d[0]), "+f"(d[1]), "+f"(d[2]), "+f"(d[3])
        : "r"(a[0]), "r"(a[1]), "r"(a[2]), "r"(a[3]), "r"(b0), "r"(b1));
}
__device__ __forceinline__ void cpa16(u32 dst, const void* src) {
    asm volatile("cp.async.ca.shared.global [%0], [%1], 16;" :: "r"(dst), "l"(src) : "memory");
}
#define CP_COMMIT() asm volatile("cp.async.commit_group;" ::: "memory")
#define CP_WAIT0()  asm volatile("cp.async.wait_group 0;" ::: "memory")
#define CP_WAIT1()  asm volatile("cp.async.wait_group 1;" ::: "memory")

__device__ __align__(16) float g_xn[NB*CH*HW];
__device__ __align__(16) u16 g_xh[NB*CH*HW];
__device__ __align__(16) u16 g_xl[NB*CH*HW];
__device__ __align__(16) u16 g_wqh[CH*384], g_wql[CH*384];
__device__ __align__(16) u16 g_woh[CH*CH],  g_wol[CH*CH];
__device__ __align__(16) u16 g_qhl[(size_t)NB*NHD*HW*64];
__device__ __align__(16) u16 g_khl[(size_t)NB*NHD*HW*64];
__device__ __align__(16) u16 g_vth[(size_t)NB*NHD*32*HW];
__device__ __align__(16) u16 g_vtl[(size_t)NB*NHD*32*HW];
__device__ __align__(16) float g_po[(size_t)1024*128*32];
__device__ __align__(16) float g_pl[1024*128];
__device__ __align__(16) u16 g_oh[NB*CH*HW];
__device__ __align__(16) u16 g_ol[NB*CH*HW];
__device__ __align__(16) float g_pj[NB*CH*HW];
__device__ __align__(16) float2 g_st1[NB*CH];
__device__ __align__(16) float2 g_st2[NB*CH];

__device__ __forceinline__ void splitbf(float v, u16* hp, u16* lp) {
    u32 u = __float_as_uint(v);
    *hp = (u16)(u >> 16);
    float r = v - __uint_as_float(u & 0xffff0000u);
    u16 lo; asm("cvt.rn.bf16.f32 %0, %1;" : "=h"(lo) : "f"(r));
    *lp = lo;
}

__global__ __launch_bounds__(256) void wsplit_kernel(const float* __restrict__ wq,
                                                     const float* __restrict__ wo) {
    int i = blockIdx.x * 256 + threadIdx.x;
    if (i < CH * 384) {
        splitbf(wq[i], &g_wqh[i], &g_wql[i]);
    } else {
        int j = i - CH * 384;
        splitbf(wo[j], &g_woh[j], &g_wol[j]);
    }
}

// ---- GroupNorm two-phase ---------------------------------------------------
__global__ __launch_bounds__(256) void gn_reduce_kernel(const float* __restrict__ src,
                                                        int which) {
    int b = blockIdx.x, tid = threadIdx.x;
    const float* xp = src + (size_t)b * 4096;
    float s = 0.f, q = 0.f;
    #pragma unroll
    for (int t = 0; t < 4; t++) {
        float4 v = *(const float4*)(xp + (t * 256 + tid) * 4);
        s += (v.x + v.y) + (v.z + v.w);
        q += (v.x * v.x + v.y * v.y) + (v.z * v.z + v.w * v.w);
    }
    #pragma unroll
    for (int o = 16; o; o >>= 1) {
        s += __shfl_xor_sync(0xffffffffu, s, o);
        q += __shfl_xor_sync(0xffffffffu, q, o);
    }
    __shared__ float2 ws[8];
    if ((tid & 31) == 0) ws[tid >> 5] = make_float2(s, q);
    __syncthreads();
    if (tid == 0) {
        float S = 0.f, Q = 0.f;
        #pragma unroll
        for (int i = 0; i < 8; i++) { S += ws[i].x; Q += ws[i].y; }
        (which ? g_st2 : g_st1)[b] = make_float2(S, Q);
    }
}

__global__ __launch_bounds__(256) void gn1_apply_kernel(const float* __restrict__ x,
                                                        const float* __restrict__ sc,
                                                        const float* __restrict__ off) {
    int b = blockIdx.x, tid = threadIdx.x;
    int c = b & 127, gb = b & ~7;
    float S = 0.f, Q = 0.f;
    #pragma unroll
    for (int j = 0; j < 8; j++) { float2 t = g_st1[gb + j]; S += t.x; Q += t.y; }
    float mu = S / 32768.f, var = Q / 32768.f - mu * mu, r = rsqrtf(var + EPSF);
    float a = r * sc[c], o = off[c] - mu * a;
    size_t base = (size_t)b * 4096;
    #pragma unroll
    for (int t = 0; t < 4; t++) {
        int i = (t * 256 + tid) * 4;
        float4 v = *(const float4*)(x + base + i);
        float4 y = make_float4(v.x * a + o, v.y * a + o, v.z * a + o, v.w * a + o);
        *(float4*)(g_xn + base + i) = y;
        u16 h[4], l[4];
        splitbf(y.x, &h[0], &l[0]); splitbf(y.y, &h[1], &l[1]);
        splitbf(y.z, &h[2], &l[2]); splitbf(y.w, &h[3], &l[3]);
        *(ull*)(g_xh + base + i) = *(ull*)h;
        *(ull*)(g_xl + base + i) = *(ull*)l;
    }
}

__global__ __launch_bounds__(256) void gn2_apply_kernel(const float* __restrict__ sc,
                                                        const float* __restrict__ off,
                                                        float* __restrict__ out) {
    int b = blockIdx.x, tid = threadIdx.x;
    int c = b & 127, gb = b & ~7;
    float S = 0.f, Q = 0.f;
    #pragma unroll
    for (int j = 0; j < 8; j++) { float2 t = g_st2[gb + j]; S += t.x; Q += t.y; }
    float mu = S / 32768.f, var = Q / 32768.f - mu * mu, r = rsqrtf(var + EPSF);
    float a = r * sc[c], o = off[c] - mu * a;
    size_t base = (size_t)b * 4096;
    #pragma unroll
    for (int t = 0; t < 4; t++) {
        int i = (t * 256 + tid) * 4;
        float4 v = *(const float4*)(g_pj + base + i);
        float4 xr = *(const float4*)(g_xn + base + i);
        *(float4*)(out + base + i) = make_float4(xr.x + v.x * a + o, xr.y + v.y * a + o,
                                                 xr.z + v.z * a + o, xr.w + v.w * a + o);
    }
}

__global__ __launch_bounds__(256) void gn_reduce_pj_kernel() {
    int b = blockIdx.x, tid = threadIdx.x;
    const float* xp = g_pj + (size_t)b * 4096;
    float s = 0.f, q = 0.f;
    #pragma unroll
    for (int t = 0; t < 4; t++) {
        float4 v = *(const float4*)(xp + (t * 256 + tid) * 4);
        s += (v.x + v.y) + (v.z + v.w);
        q += (v.x * v.x + v.y * v.y) + (v.z * v.z + v.w * v.w);
    }
    #pragma unroll
    for (int o = 16; o; o >>= 1) {
        s += __shfl_xor_sync(0xffffffffu, s, o);
        q += __shfl_xor_sync(0xffffffffu, q, o);
    }
    __shared__ float2 ws[8];
    if ((tid & 31) == 0) ws[tid >> 5] = make_float2(s, q);
    __syncthreads();
    if (tid == 0) {
        float S = 0.f, Q = 0.f;
        #pragma unroll
        for (int i = 0; i < 8; i++) { S += ws[i].x; Q += ws[i].y; }
        g_st2[b] = make_float2(S, Q);
    }
}

// ---- 1x1-conv GEMM: pipelined 2-group staging ------------------------------
#define SMC_BYTES 73728

__global__ __launch_bounds__(256) void conv_kernel(const float* __restrict__ bias,
                                                   int D, int mode) {
    extern __shared__ u16 cs[];
    u32 sb = smem_u32(cs);
    int tid = threadIdx.x, lane = tid & 31, wp = tid >> 5;
    int p0 = blockIdx.x * 64, d0 = blockIdx.y * 64, n = blockIdx.z;
    int lrow = lane & 7, lt = lane >> 3;

    const u16* wh = (mode ? g_woh : g_wqh) + d0;
    const u16* wl = (mode ? g_wol : g_wql) + d0;
    const u16* xh = (mode ? g_oh : g_xh) + (size_t)n * CH * HW + p0;
    const u16* xl = (mode ? g_ol : g_xl) + (size_t)n * CH * HW + p0;

    // group A: c-rows 0..63 of all 4 matrices; group B: c-rows 64..127
    #pragma unroll
    for (int g = 0; g < 2; g++) {
        #pragma unroll
        for (int t = 0; t < 8; t++) {
            int i = tid + t * 256;               // 0..2047
            int mat = i >> 9, m = i & 511;
            int r = g * 64 + (m >> 3), ch = m & 7;
            const u16* src;
            if (mat == 0)      src = wh + (size_t)r * D;
            else if (mat == 1) src = wl + (size_t)r * D;
            else if (mat == 2) src = xh + (size_t)r * HW;
            else               src = xl + (size_t)r * HW;
            cpa16(sb + (mat * 9216 + r * 72 + ch * 8) * 2, src + ch * 8);
        }
        CP_COMMIT();
    }

    int md = (wp & 3) * 16, np = (wp >> 2) * 32;
    float acc[4][4];
    #pragma unroll
    for (int i = 0; i < 4; i++)
        #pragma unroll
        for (int j = 0; j < 4; j++) acc[i][j] = 0.f;

    CP_WAIT1();            // group A landed
    __syncthreads();

    #pragma unroll
    for (int kc = 0; kc < 4; kc++) {
        if (kc == 2) { CP_WAIT0(); __syncthreads(); }   // group B landed
        u32 ah0[4], ah1[4], al0[4], al1[4];
        u32 ab = (kc * 32 + (lt >> 1) * 8 + lrow) * 72 + md + (lt & 1) * 8;
        ldm4t(ah0, sb + ab * 2);
        ldm4t(ah1, sb + (ab + 16 * 72) * 2);
        ldm4t(al0, sb + (9216 + ab) * 2);
        ldm4t(al1, sb + (9216 + ab + 16 * 72) * 2);
        u32 bh[4][4], bl[4][4];
        #pragma unroll
        for (int nb = 0; nb < 4; nb++) {
            u32 bb = (kc * 32 + lt * 8 + lrow) * 72 + np + nb * 8;
            ldm4t(bh[nb], sb + (18432 + bb) * 2);
            ldm4t(bl[nb], sb + (27648 + bb) * 2);
        }
        #pragma unroll
        for (int nb = 0; nb < 4; nb++) {
            mma_bf16(acc[nb], ah0, bh[nb][0], bh[nb][1]);
            mma_bf16(acc[nb], ah1, bh[nb][2], bh[nb][3]);
            mma_bf16(acc[nb], ah0, bl[nb][0], bl[nb][1]);
            mma_bf16(acc[nb], ah1, bl[nb][2], bl[nb][3]);
            mma_bf16(acc[nb], al0, bh[nb][0], bh[nb][1]);
            mma_bf16(acc[nb], al1, bh[nb][2], bh[nb][3]);
        }
    }

    __syncthreads();
    float* Of = (float*)cs;
    bool tr = (mode == 0) && (d0 < 256);
    {
        int r = md + (lane >> 2), c2 = (lane & 3) * 2;
        #pragma unroll
        for (int nb = 0; nb < 4; nb++) {
            int col = np + nb * 8 + c2;
            if (tr) {
                Of[col * 68 + r]           = acc[nb][0];
                Of[(col + 1) * 68 + r]     = acc[nb][1];
                Of[col * 68 + r + 8]       = acc[nb][2];
                Of[(col + 1) * 68 + r + 8] = acc[nb][3];
            } else {
                Of[r * 68 + col]           = acc[nb][0];
                Of[r * 68 + col + 1]       = acc[nb][1];
                Of[(r + 8) * 68 + col]     = acc[nb][2];
                Of[(r + 8) * 68 + col + 1] = acc[nb][3];
            }
        }
    }
    __syncthreads();

    if (mode == 0) {
        if (d0 < 256) {
            int unit = tid >> 1, half = tid & 1;
            int pl = unit >> 1, h2 = unit & 1;
            int p = p0 + pl;
            bool isQ = (d0 < 128);
            float scale = isQ ? QS : 1.f;
            int nh = n * 4 + ((isQ ? d0 : d0 - 128) >> 5) + h2;
            u16 hb[16], lb[16];
            #pragma unroll
            for (int j = 0; j < 16; j++) {
                int dl = h2 * 32 + half * 16 + j;
                float v = (Of[pl * 68 + dl] + bias[d0 + dl]) * scale;
                splitbf(v, &hb[j], &lb[j]);
            }
            u16* dst = (isQ ? g_qhl : g_khl) + ((size_t)nh * HW + p) * 64 + half * 16;
            *(uint4*)dst        = *(uint4*)hb;
            *(uint4*)(dst + 8)  = *(uint4*)(hb + 8);
            *(uint4*)(dst + 32) = *(uint4*)lb;
            *(uint4*)(dst + 40) = *(uint4*)(lb + 8);
        } else {
            int pg = tid & 3, dl = tid >> 2;
            int dd = d0 - 256 + dl, nh = n * 4 + (dd >> 5), jj = dd & 31;
            float bv = bias[d0 + dl];
            u16 hb[16], lb[16];
            #pragma unroll
            for (int j = 0; j < 16; j++) {
                float v = Of[dl * 68 + pg * 16 + j] + bv;
                splitbf(v, &hb[j], &lb[j]);
            }
            size_t o = ((size_t)nh * 32 + jj) * HW + p0 + pg * 16;
            *(uint4*)(g_vth + o)     = *(uint4*)hb;
            *(uint4*)(g_vth + o + 8) = *(uint4*)(hb + 8);
            *(uint4*)(g_vtl + o)     = *(uint4*)lb;
            *(uint4*)(g_vtl + o + 8) = *(uint4*)(lb + 8);
        }
    } else {
        int pg = tid & 3, dl = tid >> 2;
        float bv = bias[d0 + dl];
        float vb4[16];
        #pragma unroll
        for (int j = 0; j < 16; j++) vb4[j] = Of[dl * 68 + pg * 16 + j] + bv;
        float* dst = g_pj + ((size_t)n * CH + d0 + dl) * HW + p0 + pg * 16;
        #pragma unroll
        for (int j = 0; j < 4; j++) *(float4*)(dst + 4 * j) = *(float4*)(vb4 + 4 * j);
    }
}

// ---- Flash attention partial: Q/KV0 staging overlapped ---------------------
#define SMA_BYTES 75776

__device__ __forceinline__ void stage_kv_async(u32 sb, int nh, int kg, int buf, int tid) {
    int k0 = kg * 128;
    const uint4* ks = (const uint4*)(g_khl + (size_t)nh * HW * 64) + (size_t)k0 * 8;
    u32 kb = buf * 10240;
    #pragma unroll
    for (int t = 0; t < 4; t++) {
        int i = tid + t * 256;
        int r = i >> 3, c = i & 7;
        u32 off = kb + (c < 4 ? 0 : 5120) + r * 40 + (c & 3) * 8;
        cpa16(sb + off * 2, ks + i);
    }
    const uint4* vhs = (const uint4*)(g_vth + (size_t)nh * 32 * HW);
    const uint4* vls = (const uint4*)(g_vtl + (size_t)nh * 32 * HW);
    u32 vb = 20480 + buf * 8704;
    #pragma unroll
    for (int t = 0; t < 2; t++) {
        int i = tid + t * 256;
        int r = (i >> 4) & 31, c = i & 15;
        const uint4* srch = vhs + (size_t)r * (HW / 8) + (k0 >> 3) + c;
        const uint4* srcl = vls + (size_t)r * (HW / 8) + (k0 >> 3) + c;
        u32 off = vb + r * 136 + c * 8;
        cpa16(sb + off * 2, srch);
        cpa16(sb + (off + 4352) * 2, srcl);
    }
}

__global__ __launch_bounds__(256, 3) void attn_kernel() {
    extern __shared__ u16 sm[];
    u32 sb = smem_u32(sm);
    int tid = threadIdx.x, lane = tid & 31, w = tid >> 5;
    int nh = blockIdx.y, kq = blockIdx.z;
    int q0 = blockIdx.x * 128;
    int unit = ((blockIdx.x * 8 + nh) * 4 + kq);
    int lrow = lane & 7, lt = lane >> 3;

    // Stage Q into K-buf0 region (group 1) and KV tile 0 into buf1 (group 2).
    {
        const uint4* qsrc = (const uint4*)(g_qhl + ((size_t)nh * HW + q0) * 64);
        #pragma unroll
        for (int t = 0; t < 4; t++) {
            int i = tid + t * 256;
            int r = i >> 3, c = i & 7;
            u32 off = (c < 4 ? 0 : 5120) + r * 40 + (c & 3) * 8;
            cpa16(sb + off * 2, qsrc + i);
        }
        CP_COMMIT();
        stage_kv_async(sb, nh, kq * 8, 1, tid);
        CP_COMMIT();
        CP_WAIT1();                        // Q landed; KV0 still in flight
        __syncthreads();
    }
    u32 qh[2][4], ql[2][4];
    #pragma unroll
    for (int ks = 0; ks < 2; ks++) {
        u32 base = (16 * w + (lt & 1) * 8 + lrow) * 40 + ks * 16 + (lt >> 1) * 8;
        ldm4(qh[ks], sb + base * 2);
        ldm4(ql[ks], sb + (base + 5120) * 2);
    }
    __syncthreads();                       // Q region (buf0) free for kt=1 staging

    float O0[4] = {0,0,0,0}, O1[4] = {0,0,0,0}, O2[4] = {0,0,0,0}, O3[4] = {0,0,0,0};
    float l0 = 0.f, l1 = 0.f;

    for (int kt = 0; kt < 8; kt++) {
        int buf = (kt & 1) ^ 1;            // kt0 -> buf1, kt1 -> buf0, ...
        CP_WAIT0();
        __syncthreads();
        if (kt + 1 < 8) { stage_kv_async(sb, nh, kq * 8 + kt + 1, buf ^ 1, tid); CP_COMMIT(); }

        u32 kh = buf * 10240, kl = kh + 5120;
        u32 vth = 20480 + buf * 8704, vtl = vth + 4352;

        #pragma unroll 1
        for (int sk = 0; sk < 8; sk++) {
            u32 bh0[4], bh1[4], bl0[4], bl1[4];
            u32 kb = (sk * 16 + lrow) * 40 + lt * 8;
            ldm4(bh0, sb + (kh + kb) * 2);
            ldm4(bh1, sb + (kh + kb + 320) * 2);
            ldm4(bl0, sb + (kl + kb) * 2);
            ldm4(bl1, sb + (kl + kb + 320) * 2);

            float c0[4] = {0,0,0,0}, c1[4] = {0,0,0,0};
            mma_bf16(c0, qh[0], bh0[0], bh0[1]); mma_bf16(c0, qh[1], bh0[2], bh0[3]);
            mma_bf16(c0, qh[0], bl0[0], bl0[1]); mma_bf16(c0, qh[1], bl0[2], bl0[3]);
            mma_bf16(c0, ql[0], bh0[0], bh0[1]); mma_bf16(c0, ql[1], bh0[2], bh0[3]);
            mma_bf16(c1, qh[0], bh1[0], bh1[1]); mma_bf16(c1, qh[1], bh1[2], bh1[3]);
            mma_bf16(c1, qh[0], bl1[0], bl1[1]); mma_bf16(c1, qh[1], bl1[2], bl1[3]);
            mma_bf16(c1, ql[0], bh1[0], bh1[1]); mma_bf16(c1, ql[1], bh1[2], bh1[3]);

            float p00 = ex2f(c0[0]), p01 = ex2f(c0[1]), p02 = ex2f(c0[2]), p03 = ex2f(c0[3]);
            float p10 = ex2f(c1[0]), p11 = ex2f(c1[1]), p12 = ex2f(c1[2]), p13 = ex2f(c1[3]);
            l0 += (p00 + p01) + (p10 + p11);
            l1 += (p02 + p03) + (p12 + p13);

            u32 ah[4], al[4];
            u32 u00 = __float_as_uint(p00), u01 = __float_as_uint(p01);
            u32 u02 = __float_as_uint(p02), u03 = __float_as_uint(p03);
            u32 u10 = __float_as_uint(p10), u11 = __float_as_uint(p11);
            u32 u12 = __float_as_uint(p12), u13 = __float_as_uint(p13);
            ah[0] = __byte_perm(u00, u01, 0x7632);
            ah[1] = __byte_perm(u02, u03, 0x7632);
            ah[2] = __byte_perm(u10, u11, 0x7632);
            ah[3] = __byte_perm(u12, u13, 0x7632);
            al[0] = packbf2(p00 - __uint_as_float(u00 & 0xffff0000u), p01 - __uint_as_float(u01 & 0xffff0000u));
            al[1] = packbf2(p02 - __uint_as_float(u02 & 0xffff0000u), p03 - __uint_as_float(u03 & 0xffff0000u));
            al[2] = packbf2(p10 - __uint_as_float(u10 & 0xffff0000u), p11 - __uint_as_float(u11 & 0xffff0000u));
            al[3] = packbf2(p12 - __uint_as_float(u12 & 0xffff0000u), p13 - __uint_as_float(u13 & 0xffff0000u));

            u32 vhA[4], vhB[4], vlA[4], vlB[4];
            u32 vb = (lrow + (lt >> 1) * 8) * 136 + sk * 16 + (lt & 1) * 8;
            ldm4(vhA, sb + (vth + vb) * 2);
            ldm4(vhB, sb + (vth + vb + 16 * 136) * 2);
            ldm4(vlA, sb + (vtl + vb) * 2);
            ldm4(vlB, sb + (vtl + vb + 16 * 136) * 2);

            mma_bf16(O0, ah, vhA[0], vhA[1]); mma_bf16(O0, ah, vlA[0], vlA[1]); mma_bf16(O0, al, vhA[0], vhA[1]);
            mma_bf16(O1, ah, vhA[2], vhA[3]); mma_bf16(O1, ah, vlA[2], vlA[3]); mma_bf16(O1, al, vhA[2], vhA[3]);
            mma_bf16(O2, ah, vhB[0], vhB[1]); mma_bf16(O2, ah, vlB[0], vlB[1]); mma_bf16(O2, al, vhB[0], vhB[1]);
            mma_bf16(O3, ah, vhB[2], vhB[3]); mma_bf16(O3, ah, vlB[2], vlB[3]); mma_bf16(O3, al, vhB[2], vhB[3]);
        }
    }

    l0 += __shfl_xor_sync(0xffffffffu, l0, 1);
    l0 += __shfl_xor_sync(0xffffffffu, l0, 2);
    l1 += __shfl_xor_sync(0xffffffffu, l1, 1);
    l1 += __shfl_xor_sync(0xffffffffu, l1, 2);

    int r = 16 * w + (lane >> 2), c2 = (lane & 3) * 2;
    float* po = g_po + (size_t)unit * 4096;
    if ((lane & 3) == 0) {
        g_pl[unit * 128 + r]     = l0;
        g_pl[unit * 128 + r + 8] = l1;
    }
    float* Oarr[4] = {O0, O1, O2, O3};
    #pragma unroll
    for (int j = 0; j < 4; j++) {
        int dm = 8 * j + c2;
        *(float2*)(po + r * 32 + dm)       = make_float2(Oarr[j][0], Oarr[j][1]);
        *(float2*)(po + (r + 8) * 32 + dm) = make_float2(Oarr[j][2], Oarr[j][3]);
    }
}

// ---- Combine partials ------------------------------------------------------
__global__ __launch_bounds__(256) void attn_combine_kernel() {
    __shared__ float linv[128];
    __shared__ u16 smh[32 * 136], sml[32 * 136];
    int tid = threadIdx.x;
    int qt = blockIdx.x, nh = blockIdx.y;
    int n = nh >> 2, h = nh & 3;
    int ub = (qt * 8 + nh) * 4;

    if (tid < 128) {
        float l = 0.f;
        #pragma unroll
        for (int u = 0; u < 4; u++) l += g_pl[(ub + u) * 128 + tid];
        linv[tid] = 1.f / l;
    }
    __syncthreads();

    int r = tid >> 1, db = (tid & 1) * 16;
    float acc[16];
    #pragma unroll
    for (int i = 0; i < 16; i++) acc[i] = 0.f;
    #pragma unroll
    for (int u = 0; u < 4; u++) {
        const float* po = g_po + (size_t)(ub + u) * 4096 + r * 32 + db;
        #pragma unroll
        for (int i = 0; i < 4; i++) {
            float4 v = *(const float4*)(po + 4 * i);
            acc[4*i+0] += v.x; acc[4*i+1] += v.y; acc[4*i+2] += v.z; acc[4*i+3] += v.w;
        }
    }
    float inv = linv[r];
    #pragma unroll
    for (int i = 0; i < 16; i++) {
        u16 hh, ll;
        splitbf(acc[i] * inv, &hh, &ll);
        smh[(db + i) * 136 + r] = hh;
        sml[(db + i) * 136 + r] = ll;
    }
    __syncthreads();

    int dim = tid >> 3, ridx = (tid & 7) * 16;
    size_t o = ((size_t)n * CH + h * 32 + dim) * HW + qt * 128 + ridx;
    *(uint4*)(g_oh + o)     = *(uint4*)(smh + dim * 136 + ridx);
    *(uint4*)(g_oh + o + 8) = *(uint4*)(smh + dim * 136 + ridx + 8);
    *(uint4*)(g_ol + o)     = *(uint4*)(sml + dim * 136 + ridx);
    *(uint4*)(g_ol + o + 8) = *(uint4*)(sml + dim * 136 + ridx + 8);
}

// ---------------------------------------------------------------------------
extern "C" void kernel_launch(void* const* d_in, const int* in_sizes, int n_in,
                              void* d_out, int out_size) {
    const float* x      = (const float*)d_in[0];
    const float* w_qkv  = (const float*)d_in[1];
    const float* b_qkv  = (const float*)d_in[2];
    const float* w_out  = (const float*)d_in[3];
    const float* b_out  = (const float*)d_in[4];
    const float* gn1_s  = (const float*)d_in[5];
    const float* gn1_o  = (const float*)d_in[6];
    const float* gn2_s  = (const float*)d_in[7];
    const float* gn2_o  = (const float*)d_in[8];
    float* out = (float*)d_out;

    cudaFuncSetAttribute(attn_kernel, cudaFuncAttributeMaxDynamicSharedMemorySize, SMA_BYTES);
    cudaFuncSetAttribute(conv_kernel, cudaFuncAttributeMaxDynamicSharedMemorySize, SMC_BYTES);

    wsplit_kernel<<<256, 256>>>(w_qkv, w_out);
    gn_reduce_kernel<<<256, 256>>>(x, 0);
    gn1_apply_kernel<<<256, 256>>>(x, gn1_s, gn1_o);
    conv_kernel<<<dim3(64, 6, NB), 256, SMC_BYTES>>>(b_qkv, 384, 0);
    attn_kernel<<<dim3(32, 8, 4), 256, SMA_BYTES>>>();
    attn_combine_kernel<<<dim3(32, 8), 256>>>();
    conv_kernel<<<dim3(64, 2, NB), 256, SMC_BYTES>>>(b_out, 128, 1);
    gn_reduce_pj_kernel<<<256, 256>>>();
    gn2_apply_kernel<<<256, 256>>>(gn2_s, gn2_o, out);
}